// round 1
// baseline (speedup 1.0000x reference)
#include <cuda_runtime.h>
#include <cuda_bf16.h>
#include <math.h>

// Problem constants
#define BB 4
#define SS 2048
#define DD 512
#define HH 8
#define DHH 64
#define FF 2048
#define LL 6
#define NROWS (BB*SS)   // 8192

// ---------------------------------------------------------------------------
// Scratch (static device globals; no allocation allowed)
// ---------------------------------------------------------------------------
__device__ float g_q[NROWS * DD];
__device__ float g_k[NROWS * DD];
__device__ float g_v[NROWS * DD];
__device__ float g_t[NROWS * DD];
__device__ float g_h[NROWS * FF];

// ---------------------------------------------------------------------------
// Embedding gather: x[row] = emb[source[row]]
// ---------------------------------------------------------------------------
__global__ __launch_bounds__(128) void embed_kernel(const int* __restrict__ src,
                                                    const float* __restrict__ emb,
                                                    float* __restrict__ x) {
    int row = blockIdx.x;
    int tok = src[row];
    const float4* s = (const float4*)(emb + (size_t)tok * DD);
    float4* d = (float4*)(x + (size_t)row * DD);
    d[threadIdx.x] = s[threadIdx.x];
}

// ---------------------------------------------------------------------------
// Tiled fp32 GEMM: C[M,N] = A[M,K] @ B[K,N] + bias[N], optional relu
// BM=BN=128, BK=16, 256 threads, 8x8 micro-tile split as 4+4 (conflict-free)
// All dims assumed multiples of tile sizes (true here).
// ---------------------------------------------------------------------------
#define GBM 128
#define GBN 128
#define GBK 16

__global__ __launch_bounds__(256) void gemm_kernel(const float* __restrict__ A,
                                                   const float* __restrict__ B,
                                                   const float* __restrict__ bias,
                                                   float* __restrict__ C,
                                                   int M, int N, int K, int relu) {
    __shared__ float As[GBK][GBM + 4];
    __shared__ float Bs[GBK][GBN];

    const int tid = threadIdx.x;
    const int bm = blockIdx.y * GBM;
    const int bn = blockIdx.x * GBN;

    const int tx = tid & 15;        // 0..15
    const int ty = tid >> 4;        // 0..15
    const int r0 = ty * 4;          // rows r0..r0+3 and r0+64..r0+67
    const int c0 = tx * 4;          // cols c0..c0+3 and c0+64..c0+67

    float acc[8][8];
#pragma unroll
    for (int i = 0; i < 8; i++)
#pragma unroll
        for (int j = 0; j < 8; j++) acc[i][j] = 0.f;

    for (int bk = 0; bk < K; bk += GBK) {
        // Load A tile (BMxBK) transposed into As
#pragma unroll
        for (int i = 0; i < 2; i++) {
            int idx = i * 256 + tid;            // 0..511
            int arow = idx >> 2;                // 0..127
            int ac4 = (idx & 3) << 2;           // 0,4,8,12
            float4 va = *(const float4*)&A[(size_t)(bm + arow) * K + bk + ac4];
            As[ac4 + 0][arow] = va.x;
            As[ac4 + 1][arow] = va.y;
            As[ac4 + 2][arow] = va.z;
            As[ac4 + 3][arow] = va.w;
        }
        // Load B tile (BKxBN)
#pragma unroll
        for (int i = 0; i < 2; i++) {
            int idx = i * 256 + tid;
            int brow = idx >> 5;                // 0..15
            int bc4 = (idx & 31) << 2;          // 0..124
            *(float4*)&Bs[brow][bc4] =
                *(const float4*)&B[(size_t)(bk + brow) * N + bn + bc4];
        }
        __syncthreads();

#pragma unroll
        for (int kk = 0; kk < GBK; kk++) {
            float a[8], b[8];
            *(float4*)&a[0] = *(const float4*)&As[kk][r0];
            *(float4*)&a[4] = *(const float4*)&As[kk][r0 + 64];
            *(float4*)&b[0] = *(const float4*)&Bs[kk][c0];
            *(float4*)&b[4] = *(const float4*)&Bs[kk][c0 + 64];
#pragma unroll
            for (int i = 0; i < 8; i++)
#pragma unroll
                for (int j = 0; j < 8; j++) acc[i][j] = fmaf(a[i], b[j], acc[i][j]);
        }
        __syncthreads();
    }

    // Epilogue: bias (+relu), vectorized stores
#pragma unroll
    for (int ii = 0; ii < 2; ii++) {
#pragma unroll
        for (int i2 = 0; i2 < 4; i2++) {
            int row = bm + ii * 64 + r0 + i2;
            int ai = ii * 4 + i2;
#pragma unroll
            for (int jj = 0; jj < 2; jj++) {
                int col = bn + jj * 64 + c0;
                float4 o;
                o.x = acc[ai][jj * 4 + 0] + bias[col + 0];
                o.y = acc[ai][jj * 4 + 1] + bias[col + 1];
                o.z = acc[ai][jj * 4 + 2] + bias[col + 2];
                o.w = acc[ai][jj * 4 + 3] + bias[col + 3];
                if (relu) {
                    o.x = fmaxf(o.x, 0.f); o.y = fmaxf(o.y, 0.f);
                    o.z = fmaxf(o.z, 0.f); o.w = fmaxf(o.w, 0.f);
                }
                *(float4*)&C[(size_t)row * N + col] = o;
            }
        }
    }
}

// ---------------------------------------------------------------------------
// Flash attention, causal, fp32. Tiles 64x64, Dh=64.
// grid = (S/64, B*H), 256 threads. q/k/v layout [B,S,D] with head h at cols h*64.
// Dynamic smem: Qs,Ks,Vs,Ps each 64x68 floats.
// ---------------------------------------------------------------------------
#define ATT_PITCH 68
#define ATT_SMEM (4 * 64 * ATT_PITCH * (int)sizeof(float))

__global__ __launch_bounds__(256) void attn_kernel(const float* __restrict__ q,
                                                   const float* __restrict__ k,
                                                   const float* __restrict__ v,
                                                   float* __restrict__ out) {
    extern __shared__ float sm[];
    float* Qs = sm;
    float* Ks = Qs + 64 * ATT_PITCH;
    float* Vs = Ks + 64 * ATT_PITCH;
    float* Ps = Vs + 64 * ATT_PITCH;

    const int tid = threadIdx.x;
    const int qt = blockIdx.x;          // q tile index
    const int bh = blockIdx.y;
    const int b = bh / HH;
    const int h = bh % HH;
    const int q0 = qt * 64;

    const int cg = tid & 15;
    const int rg = tid >> 4;
    const int r0 = rg * 4;
    const int c0 = cg * 4;

    const float* qbase = q + ((size_t)(b * SS + q0) * DD + h * DHH);

    // Load Q tile
#pragma unroll
    for (int i = 0; i < 4; i++) {
        int idx = i * 256 + tid;
        int row = idx >> 4;
        int cc4 = (idx & 15) << 2;
        *(float4*)&Qs[row * ATT_PITCH + cc4] =
            *(const float4*)&qbase[(size_t)row * DD + cc4];
    }

    float o[4][4];
    float m[4], l[4];
#pragma unroll
    for (int i = 0; i < 4; i++) {
        m[i] = -1e30f; l[i] = 0.f;
#pragma unroll
        for (int j = 0; j < 4; j++) o[i][j] = 0.f;
    }

    const float scale = 0.125f;  // 1/sqrt(64)

    for (int kt = 0; kt <= qt; kt++) {
        const int k0 = kt * 64;
        const float* kbase = k + ((size_t)(b * SS + k0) * DD + h * DHH);
        const float* vbase = v + ((size_t)(b * SS + k0) * DD + h * DHH);
        __syncthreads();   // protect Ks/Vs from previous AV reads
#pragma unroll
        for (int i = 0; i < 4; i++) {
            int idx = i * 256 + tid;
            int row = idx >> 4;
            int cc4 = (idx & 15) << 2;
            *(float4*)&Ks[row * ATT_PITCH + cc4] =
                *(const float4*)&kbase[(size_t)row * DD + cc4];
            *(float4*)&Vs[row * ATT_PITCH + cc4] =
                *(const float4*)&vbase[(size_t)row * DD + cc4];
        }
        __syncthreads();

        // S = Q K^T (4x4 micro-tile)
        float s[4][4];
#pragma unroll
        for (int i = 0; i < 4; i++)
#pragma unroll
            for (int j = 0; j < 4; j++) s[i][j] = 0.f;

#pragma unroll
        for (int kk = 0; kk < 64; kk += 4) {
            float qa[4][4], ka[4][4];
#pragma unroll
            for (int i = 0; i < 4; i++)
                *(float4*)qa[i] = *(const float4*)&Qs[(r0 + i) * ATT_PITCH + kk];
#pragma unroll
            for (int j = 0; j < 4; j++)
                *(float4*)ka[j] = *(const float4*)&Ks[(c0 + j) * ATT_PITCH + kk];
#pragma unroll
            for (int i = 0; i < 4; i++)
#pragma unroll
                for (int j = 0; j < 4; j++)
#pragma unroll
                    for (int e = 0; e < 4; e++)
                        s[i][j] = fmaf(qa[i][e], ka[j][e], s[i][j]);
        }

        const bool diag = (kt == qt);
#pragma unroll
        for (int i = 0; i < 4; i++)
#pragma unroll
            for (int j = 0; j < 4; j++) {
                float sv = s[i][j] * scale;
                if (diag && (c0 + j > r0 + i)) sv = -1e30f;
                s[i][j] = sv;
            }

        // Online softmax (row stats reduced across the 16 cg-threads)
#pragma unroll
        for (int i = 0; i < 4; i++) {
            float mx = fmaxf(fmaxf(s[i][0], s[i][1]), fmaxf(s[i][2], s[i][3]));
#pragma unroll
            for (int off = 8; off >= 1; off >>= 1)
                mx = fmaxf(mx, __shfl_xor_sync(0xffffffffu, mx, off));
            float mnew = fmaxf(m[i], mx);
            float alpha = __expf(m[i] - mnew);
            float rs = 0.f;
#pragma unroll
            for (int j = 0; j < 4; j++) {
                float p = __expf(s[i][j] - mnew);
                Ps[(r0 + i) * ATT_PITCH + c0 + j] = p;
                rs += p;
            }
#pragma unroll
            for (int off = 8; off >= 1; off >>= 1)
                rs += __shfl_xor_sync(0xffffffffu, rs, off);
            l[i] = l[i] * alpha + rs;
            m[i] = mnew;
#pragma unroll
            for (int j = 0; j < 4; j++) o[i][j] *= alpha;
        }
        __syncthreads();

        // O += P V
#pragma unroll
        for (int cc4 = 0; cc4 < 64; cc4 += 4) {
            float pa[4][4];
#pragma unroll
            for (int i = 0; i < 4; i++)
                *(float4*)pa[i] = *(const float4*)&Ps[(r0 + i) * ATT_PITCH + cc4];
#pragma unroll
            for (int e = 0; e < 4; e++) {
                float va[4];
                *(float4*)va = *(const float4*)&Vs[(cc4 + e) * ATT_PITCH + c0];
#pragma unroll
                for (int i = 0; i < 4; i++)
#pragma unroll
                    for (int j = 0; j < 4; j++)
                        o[i][j] = fmaf(pa[i][e], va[j], o[i][j]);
            }
        }
    }

    // Normalize + store
#pragma unroll
    for (int i = 0; i < 4; i++) {
        float inv = 1.f / l[i];
        float4 ov;
        ov.x = o[i][0] * inv; ov.y = o[i][1] * inv;
        ov.z = o[i][2] * inv; ov.w = o[i][3] * inv;
        *(float4*)&out[((size_t)(b * SS + q0 + r0 + i) * DD + h * DHH + c0)] = ov;
    }
}

// ---------------------------------------------------------------------------
// Residual add + LayerNorm (in-place on x): x = LN(x + y) * g + b
// One block per row, 256 threads, 2 elems each.
// ---------------------------------------------------------------------------
__global__ __launch_bounds__(256) void add_ln_kernel(float* __restrict__ x,
                                                     const float* __restrict__ y,
                                                     const float* __restrict__ g,
                                                     const float* __restrict__ bb) {
    const int row = blockIdx.x;
    const int tid = threadIdx.x;
    float2 xv = *(const float2*)&x[(size_t)row * DD + tid * 2];
    float2 yv = *(const float2*)&y[(size_t)row * DD + tid * 2];
    float a0 = xv.x + yv.x;
    float a1 = xv.y + yv.y;

    float s = a0 + a1;
    float ss = a0 * a0 + a1 * a1;
#pragma unroll
    for (int off = 16; off >= 1; off >>= 1) {
        s += __shfl_xor_sync(0xffffffffu, s, off);
        ss += __shfl_xor_sync(0xffffffffu, ss, off);
    }
    __shared__ float sbuf[8], ssbuf[8];
    if ((tid & 31) == 0) { sbuf[tid >> 5] = s; ssbuf[tid >> 5] = ss; }
    __syncthreads();
    float ts = 0.f, tss = 0.f;
#pragma unroll
    for (int i = 0; i < 8; i++) { ts += sbuf[i]; tss += ssbuf[i]; }
    float mean = ts * (1.f / DD);
    float var = tss * (1.f / DD) - mean * mean;
    float rstd = rsqrtf(var + 1e-5f);

    int col = tid * 2;
    float2 go = *(const float2*)&g[col];
    float2 bo = *(const float2*)&bb[col];
    float2 out;
    out.x = (a0 - mean) * rstd * go.x + bo.x;
    out.y = (a1 - mean) * rstd * go.y + bo.y;
    *(float2*)&x[(size_t)row * DD + col] = out;
}

// ---------------------------------------------------------------------------
// Host driver
// ---------------------------------------------------------------------------
extern "C" void kernel_launch(void* const* d_in, const int* in_sizes, int n_in,
                              void* d_out, int out_size) {
    const int* source = (const int*)d_in[0];
    const float* emb = (const float*)d_in[1];
    const float* ln_g = (const float*)d_in[2];
    const float* ln_b = (const float*)d_in[3];
    const float* wq = (const float*)d_in[4];
    const float* bq = (const float*)d_in[5];
    const float* wk = (const float*)d_in[6];
    const float* bk = (const float*)d_in[7];
    const float* wv = (const float*)d_in[8];
    const float* bv = (const float*)d_in[9];
    const float* wo = (const float*)d_in[10];
    const float* bo = (const float*)d_in[11];
    const float* w1 = (const float*)d_in[12];
    const float* b1 = (const float*)d_in[13];
    const float* w2 = (const float*)d_in[14];
    const float* b2 = (const float*)d_in[15];

    float* x = (float*)d_out;   // residual stream lives in d_out

    float *q, *k, *v, *t, *hbuf;
    cudaGetSymbolAddress((void**)&q, g_q);
    cudaGetSymbolAddress((void**)&k, g_k);
    cudaGetSymbolAddress((void**)&v, g_v);
    cudaGetSymbolAddress((void**)&t, g_t);
    cudaGetSymbolAddress((void**)&hbuf, g_h);

    cudaFuncSetAttribute(attn_kernel, cudaFuncAttributeMaxDynamicSharedMemorySize,
                         ATT_SMEM);

    embed_kernel<<<NROWS, 128>>>(source, emb, x);

    dim3 gD(DD / GBN, NROWS / GBM);    // N=512 GEMMs
    dim3 gF(FF / GBN, NROWS / GBM);    // N=2048 GEMM
    dim3 gA(SS / 64, BB * HH);         // attention

    for (int l = 0; l < LL; l++) {
        const float* Wq = wq + (size_t)l * DD * DD;
        const float* Bq = bq + (size_t)l * DD;
        const float* Wk = wk + (size_t)l * DD * DD;
        const float* Bk = bk + (size_t)l * DD;
        const float* Wv = wv + (size_t)l * DD * DD;
        const float* Bv = bv + (size_t)l * DD;
        const float* Wo = wo + (size_t)l * DD * DD;
        const float* Bo = bo + (size_t)l * DD;
        const float* W1 = w1 + (size_t)l * DD * FF;
        const float* B1 = b1 + (size_t)l * FF;
        const float* W2 = w2 + (size_t)l * FF * DD;
        const float* B2 = b2 + (size_t)l * DD;

        gemm_kernel<<<gD, 256>>>(x, Wq, Bq, q, NROWS, DD, DD, 0);
        gemm_kernel<<<gD, 256>>>(x, Wk, Bk, k, NROWS, DD, DD, 0);
        gemm_kernel<<<gD, 256>>>(x, Wv, Bv, v, NROWS, DD, DD, 0);

        attn_kernel<<<gA, 256, ATT_SMEM>>>(q, k, v, t);

        gemm_kernel<<<gD, 256>>>(t, Wo, Bo, q, NROWS, DD, DD, 0);   // q reused as proj
        add_ln_kernel<<<NROWS, 256>>>(x, q, ln_g, ln_b);

        gemm_kernel<<<gF, 256>>>(x, W1, B1, hbuf, NROWS, FF, DD, 1);
        gemm_kernel<<<gD, 256>>>(hbuf, W2, B2, t, NROWS, DD, FF, 1);
        add_ln_kernel<<<NROWS, 256>>>(x, t, ln_g, ln_b);
    }
}

// round 3
// speedup vs baseline: 1.3041x; 1.3041x over previous
#include <cuda_runtime.h>
#include <cuda_bf16.h>
#include <math.h>
#include <stdint.h>

// Problem constants
#define BB 4
#define SS 2048
#define DD 512
#define HH 8
#define DHH 64
#define FF 2048
#define LL 6
#define NROWS (BB*SS)   // 8192

// ---------------------------------------------------------------------------
// Scratch (static device globals; no allocation allowed)
// ---------------------------------------------------------------------------
__device__ float g_q[NROWS * DD];
__device__ float g_k[NROWS * DD];
__device__ float g_v[NROWS * DD];
__device__ float g_t[NROWS * DD];
__device__ float g_h[NROWS * FF];
__device__ __nv_bfloat16 g_ahi[NROWS * FF];
__device__ __nv_bfloat16 g_alo[NROWS * FF];
__device__ __nv_bfloat16 g_wthi[FF * DD];
__device__ __nv_bfloat16 g_wtlo[FF * DD];

// ---------------------------------------------------------------------------
// Embedding gather
// ---------------------------------------------------------------------------
__global__ __launch_bounds__(128) void embed_kernel(const int* __restrict__ src,
                                                    const float* __restrict__ emb,
                                                    float* __restrict__ x) {
    int row = blockIdx.x;
    int tok = src[row];
    const float4* s = (const float4*)(emb + (size_t)tok * DD);
    float4* d = (float4*)(x + (size_t)row * DD);
    d[threadIdx.x] = s[threadIdx.x];
}

// ---------------------------------------------------------------------------
// fp32 -> (bf16 hi, bf16 lo) split, elementwise
// ---------------------------------------------------------------------------
__global__ __launch_bounds__(256) void cvt_split_kernel(const float* __restrict__ X,
                                                        __nv_bfloat16* __restrict__ hi,
                                                        __nv_bfloat16* __restrict__ lo,
                                                        int n4) {
    int i = blockIdx.x * 256 + threadIdx.x;
    if (i >= n4) return;
    float4 v = ((const float4*)X)[i];
    __nv_bfloat16 h0 = __float2bfloat16_rn(v.x);
    __nv_bfloat16 h1 = __float2bfloat16_rn(v.y);
    __nv_bfloat16 h2 = __float2bfloat16_rn(v.z);
    __nv_bfloat16 h3 = __float2bfloat16_rn(v.w);
    __nv_bfloat16 l0 = __float2bfloat16_rn(v.x - __bfloat162float(h0));
    __nv_bfloat16 l1 = __float2bfloat16_rn(v.y - __bfloat162float(h1));
    __nv_bfloat16 l2 = __float2bfloat16_rn(v.z - __bfloat162float(h2));
    __nv_bfloat16 l3 = __float2bfloat16_rn(v.w - __bfloat162float(h3));
    __nv_bfloat162* H = (__nv_bfloat162*)hi;
    __nv_bfloat162* L = (__nv_bfloat162*)lo;
    H[2 * i]     = __nv_bfloat162(h0, h1);
    H[2 * i + 1] = __nv_bfloat162(h2, h3);
    L[2 * i]     = __nv_bfloat162(l0, l1);
    L[2 * i + 1] = __nv_bfloat162(l2, l3);
}

// ---------------------------------------------------------------------------
// Transpose + split: W[K,N] fp32 -> WT_hi/WT_lo [N,K] bf16
// ---------------------------------------------------------------------------
__global__ __launch_bounds__(256) void transpose_cvt_kernel(const float* __restrict__ W,
                                                            __nv_bfloat16* __restrict__ WThi,
                                                            __nv_bfloat16* __restrict__ WTlo,
                                                            int K, int N) {
    __shared__ float t[32][33];
    int n0 = blockIdx.x * 32, k0 = blockIdx.y * 32;
    int c = threadIdx.x & 31, r = threadIdx.x >> 5;
#pragma unroll
    for (int i = 0; i < 4; i++)
        t[r + i * 8][c] = W[(size_t)(k0 + r + i * 8) * N + n0 + c];
    __syncthreads();
#pragma unroll
    for (int i = 0; i < 4; i++) {
        float x = t[c][r + i * 8];
        __nv_bfloat16 h = __float2bfloat16_rn(x);
        __nv_bfloat16 l = __float2bfloat16_rn(x - __bfloat162float(h));
        size_t o = (size_t)(n0 + r + i * 8) * K + k0 + c;
        WThi[o] = h;
        WTlo[o] = l;
    }
}

// ---------------------------------------------------------------------------
// Warp-MMA bf16x3 GEMM: C[M,N] = A[M,K] @ B[N,K]^T + bias, optional relu.
// mma.sync.m16n8k16 bf16 (baseline PTX, valid on compute_103).
// CTA 128x128, 8 warps (2x4), warp tile 64x32. K-chunk 32, cp.async double buf.
// smem pitch 40 bf16 (80B) -> conflict-free fragment loads.
// ---------------------------------------------------------------------------
#define GP_B   80                 // row pitch bytes (40 bf16)
#define GTILE_B (128 * GP_B)      // 10240 bytes per operand tile
#define GSTAGE_B (4 * GTILE_B)    // Ahi, Alo, Bhi, Blo
#define GSMEM   (2 * GSTAGE_B)    // 81920 bytes

__device__ __forceinline__ uint32_t smem_u32(const void* p) {
    uint32_t a;
    asm("{ .reg .u64 t; cvta.to.shared.u64 t, %1; cvt.u32.u64 %0, t; }"
        : "=r"(a) : "l"(p));
    return a;
}

__device__ __forceinline__ void mma16816(float* c, const uint32_t* a, const uint32_t* b) {
    asm volatile(
        "mma.sync.aligned.m16n8k16.row.col.f32.bf16.bf16.f32 "
        "{%0,%1,%2,%3}, {%4,%5,%6,%7}, {%8,%9}, {%0,%1,%2,%3};"
        : "+f"(c[0]), "+f"(c[1]), "+f"(c[2]), "+f"(c[3])
        : "r"(a[0]), "r"(a[1]), "r"(a[2]), "r"(a[3]), "r"(b[0]), "r"(b[1]));
}

__global__ __launch_bounds__(256, 1) void gemm_wm_kernel(
    const __nv_bfloat16* __restrict__ Ahi, const __nv_bfloat16* __restrict__ Alo,
    const __nv_bfloat16* __restrict__ Bhi, const __nv_bfloat16* __restrict__ Blo,
    const float* __restrict__ bias, float* __restrict__ C,
    int M, int N, int K, int relu) {
    extern __shared__ char sm[];
    const uint32_t sbase = smem_u32(sm);

    const int tid = threadIdx.x;
    const int lane = tid & 31;
    const int wid = tid >> 5;
    const int warp_m = wid >> 2;        // 0..1
    const int warp_n = wid & 3;         // 0..3
    const int g = lane >> 2;            // 0..7
    const int tig = lane & 3;           // 0..3

    const int bm = blockIdx.y * 128;
    const int bn = blockIdx.x * 128;

    const __nv_bfloat16* srcs[4] = {
        Ahi + (size_t)bm * K, Alo + (size_t)bm * K,
        Bhi + (size_t)bn * K, Blo + (size_t)bn * K };

    float acc[4][4][4];
#pragma unroll
    for (int mt = 0; mt < 4; mt++)
#pragma unroll
        for (int nt = 0; nt < 4; nt++)
#pragma unroll
            for (int e = 0; e < 4; e++) acc[mt][nt][e] = 0.f;

    const int NIT = K >> 5;   // K-chunks of 32

    // stage loader: 4 tiles x 128 rows x 32 bf16 (64B) via cp.async 16B
    auto load_stage = [&](int s, int it) {
        const uint32_t stage = sbase + (uint32_t)s * GSTAGE_B;
#pragma unroll
        for (int t = 0; t < 4; t++) {
#pragma unroll
            for (int i = 0; i < 2; i++) {
                int idx = i * 256 + tid;        // 0..511
                int r = idx >> 2;               // 0..127
                int c8 = idx & 3;               // 16B block within 64B row
                const void* src = (const char*)(srcs[t] + (size_t)r * K + it * 32) + c8 * 16;
                uint32_t dst = stage + (uint32_t)t * GTILE_B + (uint32_t)r * GP_B + c8 * 16;
                asm volatile("cp.async.cg.shared.global [%0], [%1], 16;"
                             :: "r"(dst), "l"(src));
            }
        }
        asm volatile("cp.async.commit_group;" ::: "memory");
    };

    load_stage(0, 0);

    for (int it = 0; it < NIT; it++) {
        const int buf = it & 1;
        if (it + 1 < NIT) load_stage(buf ^ 1, it + 1);
        if (it + 1 < NIT) asm volatile("cp.async.wait_group 1;" ::: "memory");
        else              asm volatile("cp.async.wait_group 0;" ::: "memory");
        __syncthreads();

        const char* A0 = sm + buf * GSTAGE_B;
        const char* A1 = A0 + GTILE_B;
        const char* B0 = A0 + 2 * GTILE_B;
        const char* B1 = A0 + 3 * GTILE_B;

#pragma unroll
        for (int ks = 0; ks < 2; ks++) {
            const int kb = ks * 32 + tig * 4;   // byte offset of 2 bf16 in k
            uint32_t ah[4][4], al[4][4], bh[4][2], bl[4][2];
#pragma unroll
            for (int mt = 0; mt < 4; mt++) {
                int off = (warp_m * 64 + mt * 16 + g) * GP_B + kb;
                ah[mt][0] = *(const uint32_t*)(A0 + off);
                ah[mt][1] = *(const uint32_t*)(A0 + off + 8 * GP_B);
                ah[mt][2] = *(const uint32_t*)(A0 + off + 16);
                ah[mt][3] = *(const uint32_t*)(A0 + off + 8 * GP_B + 16);
                al[mt][0] = *(const uint32_t*)(A1 + off);
                al[mt][1] = *(const uint32_t*)(A1 + off + 8 * GP_B);
                al[mt][2] = *(const uint32_t*)(A1 + off + 16);
                al[mt][3] = *(const uint32_t*)(A1 + off + 8 * GP_B + 16);
            }
#pragma unroll
            for (int nt = 0; nt < 4; nt++) {
                int off = (warp_n * 32 + nt * 8 + g) * GP_B + kb;
                bh[nt][0] = *(const uint32_t*)(B0 + off);
                bh[nt][1] = *(const uint32_t*)(B0 + off + 16);
                bl[nt][0] = *(const uint32_t*)(B1 + off);
                bl[nt][1] = *(const uint32_t*)(B1 + off + 16);
            }
#pragma unroll
            for (int mt = 0; mt < 4; mt++)
#pragma unroll
                for (int nt = 0; nt < 4; nt++) {
                    mma16816(acc[mt][nt], ah[mt], bh[nt]);
                    mma16816(acc[mt][nt], ah[mt], bl[nt]);
                    mma16816(acc[mt][nt], al[mt], bh[nt]);
                }
        }
        __syncthreads();
    }

    // Epilogue: bias (+relu), direct float2 stores
#pragma unroll
    for (int mt = 0; mt < 4; mt++) {
        int row0 = bm + warp_m * 64 + mt * 16 + g;
#pragma unroll
        for (int nt = 0; nt < 4; nt++) {
            int col = bn + warp_n * 32 + nt * 8 + 2 * tig;
            float bx = bias[col], by = bias[col + 1];
            float2 v0, v1;
            v0.x = acc[mt][nt][0] + bx; v0.y = acc[mt][nt][1] + by;
            v1.x = acc[mt][nt][2] + bx; v1.y = acc[mt][nt][3] + by;
            if (relu) {
                v0.x = fmaxf(v0.x, 0.f); v0.y = fmaxf(v0.y, 0.f);
                v1.x = fmaxf(v1.x, 0.f); v1.y = fmaxf(v1.y, 0.f);
            }
            *(float2*)&C[(size_t)row0 * N + col] = v0;
            *(float2*)&C[(size_t)(row0 + 8) * N + col] = v1;
        }
    }
}

// ---------------------------------------------------------------------------
// Flash attention, causal, fp32 (unchanged)
// ---------------------------------------------------------------------------
#define ATT_PITCH 68
#define ATT_SMEM (4 * 64 * ATT_PITCH * (int)sizeof(float))

__global__ __launch_bounds__(256) void attn_kernel(const float* __restrict__ q,
                                                   const float* __restrict__ k,
                                                   const float* __restrict__ v,
                                                   float* __restrict__ out) {
    extern __shared__ float smf[];
    float* Qs = smf;
    float* Ks = Qs + 64 * ATT_PITCH;
    float* Vs = Ks + 64 * ATT_PITCH;
    float* Ps = Vs + 64 * ATT_PITCH;

    const int tid = threadIdx.x;
    const int qt = blockIdx.x;
    const int bh = blockIdx.y;
    const int b = bh / HH;
    const int h = bh % HH;
    const int q0 = qt * 64;

    const int cg = tid & 15;
    const int rg = tid >> 4;
    const int r0 = rg * 4;
    const int c0 = cg * 4;

    const float* qbase = q + ((size_t)(b * SS + q0) * DD + h * DHH);
#pragma unroll
    for (int i = 0; i < 4; i++) {
        int idx = i * 256 + tid;
        int row = idx >> 4;
        int cc4 = (idx & 15) << 2;
        *(float4*)&Qs[row * ATT_PITCH + cc4] =
            *(const float4*)&qbase[(size_t)row * DD + cc4];
    }

    float o[4][4];
    float m[4], l[4];
#pragma unroll
    for (int i = 0; i < 4; i++) {
        m[i] = -1e30f; l[i] = 0.f;
#pragma unroll
        for (int j = 0; j < 4; j++) o[i][j] = 0.f;
    }

    const float scale = 0.125f;

    for (int kt = 0; kt <= qt; kt++) {
        const int k0 = kt * 64;
        const float* kbase = k + ((size_t)(b * SS + k0) * DD + h * DHH);
        const float* vbase = v + ((size_t)(b * SS + k0) * DD + h * DHH);
        __syncthreads();
#pragma unroll
        for (int i = 0; i < 4; i++) {
            int idx = i * 256 + tid;
            int row = idx >> 4;
            int cc4 = (idx & 15) << 2;
            *(float4*)&Ks[row * ATT_PITCH + cc4] =
                *(const float4*)&kbase[(size_t)row * DD + cc4];
            *(float4*)&Vs[row * ATT_PITCH + cc4] =
                *(const float4*)&vbase[(size_t)row * DD + cc4];
        }
        __syncthreads();

        float s[4][4];
#pragma unroll
        for (int i = 0; i < 4; i++)
#pragma unroll
            for (int j = 0; j < 4; j++) s[i][j] = 0.f;

#pragma unroll
        for (int kk = 0; kk < 64; kk += 4) {
            float qa[4][4], ka[4][4];
#pragma unroll
            for (int i = 0; i < 4; i++)
                *(float4*)qa[i] = *(const float4*)&Qs[(r0 + i) * ATT_PITCH + kk];
#pragma unroll
            for (int j = 0; j < 4; j++)
                *(float4*)ka[j] = *(const float4*)&Ks[(c0 + j) * ATT_PITCH + kk];
#pragma unroll
            for (int i = 0; i < 4; i++)
#pragma unroll
                for (int j = 0; j < 4; j++)
#pragma unroll
                    for (int e = 0; e < 4; e++)
                        s[i][j] = fmaf(qa[i][e], ka[j][e], s[i][j]);
        }

        const bool diag = (kt == qt);
#pragma unroll
        for (int i = 0; i < 4; i++)
#pragma unroll
            for (int j = 0; j < 4; j++) {
                float sv = s[i][j] * scale;
                if (diag && (c0 + j > r0 + i)) sv = -1e30f;
                s[i][j] = sv;
            }

#pragma unroll
        for (int i = 0; i < 4; i++) {
            float mx = fmaxf(fmaxf(s[i][0], s[i][1]), fmaxf(s[i][2], s[i][3]));
#pragma unroll
            for (int off = 8; off >= 1; off >>= 1)
                mx = fmaxf(mx, __shfl_xor_sync(0xffffffffu, mx, off));
            float mnew = fmaxf(m[i], mx);
            float alpha = __expf(m[i] - mnew);
            float rs = 0.f;
#pragma unroll
            for (int j = 0; j < 4; j++) {
                float p = __expf(s[i][j] - mnew);
                Ps[(r0 + i) * ATT_PITCH + c0 + j] = p;
                rs += p;
            }
#pragma unroll
            for (int off = 8; off >= 1; off >>= 1)
                rs += __shfl_xor_sync(0xffffffffu, rs, off);
            l[i] = l[i] * alpha + rs;
            m[i] = mnew;
#pragma unroll
            for (int j = 0; j < 4; j++) o[i][j] *= alpha;
        }
        __syncthreads();

#pragma unroll
        for (int cc4 = 0; cc4 < 64; cc4 += 4) {
            float pa[4][4];
#pragma unroll
            for (int i = 0; i < 4; i++)
                *(float4*)pa[i] = *(const float4*)&Ps[(r0 + i) * ATT_PITCH + cc4];
#pragma unroll
            for (int e = 0; e < 4; e++) {
                float va[4];
                *(float4*)va = *(const float4*)&Vs[(cc4 + e) * ATT_PITCH + c0];
#pragma unroll
                for (int i = 0; i < 4; i++)
#pragma unroll
                    for (int j = 0; j < 4; j++)
                        o[i][j] = fmaf(pa[i][e], va[j], o[i][j]);
            }
        }
    }

#pragma unroll
    for (int i = 0; i < 4; i++) {
        float inv = 1.f / l[i];
        float4 ov;
        ov.x = o[i][0] * inv; ov.y = o[i][1] * inv;
        ov.z = o[i][2] * inv; ov.w = o[i][3] * inv;
        *(float4*)&out[((size_t)(b * SS + q0 + r0 + i) * DD + h * DHH + c0)] = ov;
    }
}

// ---------------------------------------------------------------------------
// Residual add + LayerNorm (in-place on x)
// ---------------------------------------------------------------------------
__global__ __launch_bounds__(256) void add_ln_kernel(float* __restrict__ x,
                                                     const float* __restrict__ y,
                                                     const float* __restrict__ g,
                                                     const float* __restrict__ bb) {
    const int row = blockIdx.x;
    const int tid = threadIdx.x;
    float2 xv = *(const float2*)&x[(size_t)row * DD + tid * 2];
    float2 yv = *(const float2*)&y[(size_t)row * DD + tid * 2];
    float a0 = xv.x + yv.x;
    float a1 = xv.y + yv.y;

    float s = a0 + a1;
    float ss = a0 * a0 + a1 * a1;
#pragma unroll
    for (int off = 16; off >= 1; off >>= 1) {
        s += __shfl_xor_sync(0xffffffffu, s, off);
        ss += __shfl_xor_sync(0xffffffffu, ss, off);
    }
    __shared__ float sbuf[8], ssbuf[8];
    if ((tid & 31) == 0) { sbuf[tid >> 5] = s; ssbuf[tid >> 5] = ss; }
    __syncthreads();
    float ts = 0.f, tss = 0.f;
#pragma unroll
    for (int i = 0; i < 8; i++) { ts += sbuf[i]; tss += ssbuf[i]; }
    float mean = ts * (1.f / DD);
    float var = tss * (1.f / DD) - mean * mean;
    float rstd = rsqrtf(var + 1e-5f);

    int col = tid * 2;
    float2 go = *(const float2*)&g[col];
    float2 bo = *(const float2*)&bb[col];
    float2 out;
    out.x = (a0 - mean) * rstd * go.x + bo.x;
    out.y = (a1 - mean) * rstd * go.y + bo.y;
    *(float2*)&x[(size_t)row * DD + col] = out;
}

// ---------------------------------------------------------------------------
// Host driver
// ---------------------------------------------------------------------------
static void run_gemm(const __nv_bfloat16* ahi, const __nv_bfloat16* alo,
                     const __nv_bfloat16* bhi, const __nv_bfloat16* blo,
                     const float* bias, float* C, int M, int N, int K, int relu) {
    dim3 g(N / 128, M / 128);
    gemm_wm_kernel<<<g, 256, GSMEM>>>(ahi, alo, bhi, blo, bias, C, M, N, K, relu);
}

extern "C" void kernel_launch(void* const* d_in, const int* in_sizes, int n_in,
                              void* d_out, int out_size) {
    const int* source = (const int*)d_in[0];
    const float* emb = (const float*)d_in[1];
    const float* ln_g = (const float*)d_in[2];
    const float* ln_b = (const float*)d_in[3];
    const float* wq = (const float*)d_in[4];
    const float* bq = (const float*)d_in[5];
    const float* wk = (const float*)d_in[6];
    const float* bk = (const float*)d_in[7];
    const float* wv = (const float*)d_in[8];
    const float* bv = (const float*)d_in[9];
    const float* wo = (const float*)d_in[10];
    const float* bo = (const float*)d_in[11];
    const float* w1 = (const float*)d_in[12];
    const float* b1 = (const float*)d_in[13];
    const float* w2 = (const float*)d_in[14];
    const float* b2 = (const float*)d_in[15];

    float* x = (float*)d_out;

    float *q, *k, *v, *t, *hbuf;
    __nv_bfloat16 *ahi, *alo, *wthi, *wtlo;
    cudaGetSymbolAddress((void**)&q, g_q);
    cudaGetSymbolAddress((void**)&k, g_k);
    cudaGetSymbolAddress((void**)&v, g_v);
    cudaGetSymbolAddress((void**)&t, g_t);
    cudaGetSymbolAddress((void**)&hbuf, g_h);
    cudaGetSymbolAddress((void**)&ahi, g_ahi);
    cudaGetSymbolAddress((void**)&alo, g_alo);
    cudaGetSymbolAddress((void**)&wthi, g_wthi);
    cudaGetSymbolAddress((void**)&wtlo, g_wtlo);

    cudaFuncSetAttribute(attn_kernel, cudaFuncAttributeMaxDynamicSharedMemorySize,
                         ATT_SMEM);
    cudaFuncSetAttribute(gemm_wm_kernel, cudaFuncAttributeMaxDynamicSharedMemorySize,
                         GSMEM);

    embed_kernel<<<NROWS, 128>>>(source, emb, x);

    dim3 gA(SS / 64, BB * HH);
    const int n4_D = NROWS * DD / 4;
    const int n4_F = NROWS * FF / 4;

    for (int l = 0; l < LL; l++) {
        const float* Wq = wq + (size_t)l * DD * DD;
        const float* Bq = bq + (size_t)l * DD;
        const float* Wk = wk + (size_t)l * DD * DD;
        const float* Bk = bk + (size_t)l * DD;
        const float* Wv = wv + (size_t)l * DD * DD;
        const float* Bv = bv + (size_t)l * DD;
        const float* Wo = wo + (size_t)l * DD * DD;
        const float* Bo = bo + (size_t)l * DD;
        const float* W1 = w1 + (size_t)l * DD * FF;
        const float* B1 = b1 + (size_t)l * FF;
        const float* W2 = w2 + (size_t)l * FF * DD;
        const float* B2 = b2 + (size_t)l * DD;

        // QKV projections (shared A split)
        cvt_split_kernel<<<(n4_D + 255) / 256, 256>>>(x, ahi, alo, n4_D);
        transpose_cvt_kernel<<<dim3(DD / 32, DD / 32), 256>>>(Wq, wthi, wtlo, DD, DD);
        run_gemm(ahi, alo, wthi, wtlo, Bq, q, NROWS, DD, DD, 0);
        transpose_cvt_kernel<<<dim3(DD / 32, DD / 32), 256>>>(Wk, wthi, wtlo, DD, DD);
        run_gemm(ahi, alo, wthi, wtlo, Bk, k, NROWS, DD, DD, 0);
        transpose_cvt_kernel<<<dim3(DD / 32, DD / 32), 256>>>(Wv, wthi, wtlo, DD, DD);
        run_gemm(ahi, alo, wthi, wtlo, Bv, v, NROWS, DD, DD, 0);

        attn_kernel<<<gA, 256, ATT_SMEM>>>(q, k, v, t);

        // output projection
        cvt_split_kernel<<<(n4_D + 255) / 256, 256>>>(t, ahi, alo, n4_D);
        transpose_cvt_kernel<<<dim3(DD / 32, DD / 32), 256>>>(Wo, wthi, wtlo, DD, DD);
        run_gemm(ahi, alo, wthi, wtlo, Bo, q, NROWS, DD, DD, 0);
        add_ln_kernel<<<NROWS, 256>>>(x, q, ln_g, ln_b);

        // FFN
        cvt_split_kernel<<<(n4_D + 255) / 256, 256>>>(x, ahi, alo, n4_D);
        transpose_cvt_kernel<<<dim3(FF / 32, DD / 32), 256>>>(W1, wthi, wtlo, DD, FF);
        run_gemm(ahi, alo, wthi, wtlo, B1, hbuf, NROWS, FF, DD, 1);
        cvt_split_kernel<<<(n4_F + 255) / 256, 256>>>(hbuf, ahi, alo, n4_F);
        transpose_cvt_kernel<<<dim3(DD / 32, FF / 32), 256>>>(W2, wthi, wtlo, FF, DD);
        run_gemm(ahi, alo, wthi, wtlo, B2, t, NROWS, DD, FF, 1);
        add_ln_kernel<<<NROWS, 256>>>(x, t, ln_g, ln_b);
    }
}

// round 4
// speedup vs baseline: 2.6225x; 2.0110x over previous
#include <cuda_runtime.h>
#include <cuda_bf16.h>
#include <math.h>
#include <stdint.h>

// Problem constants
#define BB 4
#define SS 2048
#define DD 512
#define HH 8
#define DHH 64
#define FF 2048
#define LL 6
#define NROWS (BB*SS)   // 8192

typedef __nv_bfloat16 bf16;

// ---------------------------------------------------------------------------
// Scratch
// ---------------------------------------------------------------------------
__device__ float g_tmp[NROWS * DD];           // fp32 proj output before add_ln
__device__ bf16 g_xhi[NROWS * DD];
__device__ bf16 g_xlo[NROWS * DD];
__device__ bf16 g_qhi[NROWS * DD];
__device__ bf16 g_qlo[NROWS * DD];
__device__ bf16 g_khi[NROWS * DD];
__device__ bf16 g_klo[NROWS * DD];
__device__ bf16 g_vhi[NROWS * DD];
__device__ bf16 g_vlo[NROWS * DD];
__device__ bf16 g_thi[NROWS * DD];
__device__ bf16 g_tlo[NROWS * DD];
__device__ bf16 g_hhi[NROWS * FF];
__device__ bf16 g_hlo[NROWS * FF];
__device__ bf16 g_wthi[FF * DD];
__device__ bf16 g_wtlo[FF * DD];

// ---------------------------------------------------------------------------
// helpers
// ---------------------------------------------------------------------------
__device__ __forceinline__ uint32_t smem_u32(const void* p) {
    uint32_t a;
    asm("{ .reg .u64 t; cvta.to.shared.u64 t, %1; cvt.u32.u64 %0, t; }"
        : "=r"(a) : "l"(p));
    return a;
}

__device__ __forceinline__ void mma16816(float* c, const uint32_t* a, const uint32_t* b) {
    asm volatile(
        "mma.sync.aligned.m16n8k16.row.col.f32.bf16.bf16.f32 "
        "{%0,%1,%2,%3}, {%4,%5,%6,%7}, {%8,%9}, {%0,%1,%2,%3};"
        : "+f"(c[0]), "+f"(c[1]), "+f"(c[2]), "+f"(c[3])
        : "r"(a[0]), "r"(a[1]), "r"(a[2]), "r"(a[3]), "r"(b[0]), "r"(b[1]));
}

__device__ __forceinline__ uint32_t pk2(float x0, float x1) {
    __nv_bfloat162 t = __floats2bfloat162_rn(x0, x1);
    return *(uint32_t*)&t;
}

// ---------------------------------------------------------------------------
// Embedding gather + split: x = emb[src], xhi/xlo = bf16 split
// ---------------------------------------------------------------------------
__global__ __launch_bounds__(128) void embed_kernel(const int* __restrict__ src,
                                                    const float* __restrict__ emb,
                                                    float* __restrict__ x,
                                                    bf16* __restrict__ xhi,
                                                    bf16* __restrict__ xlo) {
    int row = blockIdx.x;
    int tok = src[row];
    float4 v = ((const float4*)(emb + (size_t)tok * DD))[threadIdx.x];
    ((float4*)(x + (size_t)row * DD))[threadIdx.x] = v;
    float h0 = __bfloat162float(__float2bfloat16_rn(v.x));
    float h1 = __bfloat162float(__float2bfloat16_rn(v.y));
    float h2 = __bfloat162float(__float2bfloat16_rn(v.z));
    float h3 = __bfloat162float(__float2bfloat16_rn(v.w));
    uint32_t* H = (uint32_t*)(xhi + (size_t)row * DD);
    uint32_t* L = (uint32_t*)(xlo + (size_t)row * DD);
    H[2 * threadIdx.x]     = pk2(h0, h1);
    H[2 * threadIdx.x + 1] = pk2(h2, h3);
    L[2 * threadIdx.x]     = pk2(v.x - h0, v.y - h1);
    L[2 * threadIdx.x + 1] = pk2(v.z - h2, v.w - h3);
}

// ---------------------------------------------------------------------------
// Transpose + split: W[K,N] fp32 -> WT_hi/WT_lo [N,K] bf16
// ---------------------------------------------------------------------------
__global__ __launch_bounds__(256) void transpose_cvt_kernel(const float* __restrict__ W,
                                                            bf16* __restrict__ WThi,
                                                            bf16* __restrict__ WTlo,
                                                            int K, int N) {
    __shared__ float t[32][33];
    int n0 = blockIdx.x * 32, k0 = blockIdx.y * 32;
    int c = threadIdx.x & 31, r = threadIdx.x >> 5;
#pragma unroll
    for (int i = 0; i < 4; i++)
        t[r + i * 8][c] = W[(size_t)(k0 + r + i * 8) * N + n0 + c];
    __syncthreads();
#pragma unroll
    for (int i = 0; i < 4; i++) {
        float x = t[c][r + i * 8];
        bf16 h = __float2bfloat16_rn(x);
        bf16 l = __float2bfloat16_rn(x - __bfloat162float(h));
        size_t o = (size_t)(n0 + r + i * 8) * K + k0 + c;
        WThi[o] = h;
        WTlo[o] = l;
    }
}

// ---------------------------------------------------------------------------
// Warp-MMA bf16x3 GEMM. out mode 0: fp32 C; mode 1: split bf16 (Chi/Clo).
// CTA 128x128, 8 warps (2x4), warp tile 64x32, K-chunk 32, cp.async 2-stage.
// ---------------------------------------------------------------------------
#define GP_B   80
#define GTILE_B (128 * GP_B)
#define GSTAGE_B (4 * GTILE_B)
#define GSMEM   (2 * GSTAGE_B)    // 81920

__global__ __launch_bounds__(256, 2) void gemm_wm_kernel(
    const bf16* __restrict__ Ahi, const bf16* __restrict__ Alo,
    const bf16* __restrict__ Bhi, const bf16* __restrict__ Blo,
    const float* __restrict__ bias, float* __restrict__ C,
    bf16* __restrict__ Chi, bf16* __restrict__ Clo,
    int M, int N, int K, int relu, int mode) {
    extern __shared__ char sm[];
    const uint32_t sbase = smem_u32(sm);

    const int tid = threadIdx.x;
    const int lane = tid & 31;
    const int wid = tid >> 5;
    const int warp_m = wid >> 2;
    const int warp_n = wid & 3;
    const int g = lane >> 2;
    const int tig = lane & 3;

    const int bm = blockIdx.y * 128;
    const int bn = blockIdx.x * 128;

    const bf16* srcs[4] = {
        Ahi + (size_t)bm * K, Alo + (size_t)bm * K,
        Bhi + (size_t)bn * K, Blo + (size_t)bn * K };

    float acc[4][4][4];
#pragma unroll
    for (int mt = 0; mt < 4; mt++)
#pragma unroll
        for (int nt = 0; nt < 4; nt++)
#pragma unroll
            for (int e = 0; e < 4; e++) acc[mt][nt][e] = 0.f;

    const int NIT = K >> 5;

    auto load_stage = [&](int s, int it) {
        const uint32_t stage = sbase + (uint32_t)s * GSTAGE_B;
#pragma unroll
        for (int t = 0; t < 4; t++) {
#pragma unroll
            for (int i = 0; i < 2; i++) {
                int idx = i * 256 + tid;
                int r = idx >> 2;
                int c8 = idx & 3;
                const void* src = (const char*)(srcs[t] + (size_t)r * K + it * 32) + c8 * 16;
                uint32_t dst = stage + (uint32_t)t * GTILE_B + (uint32_t)r * GP_B + c8 * 16;
                asm volatile("cp.async.cg.shared.global [%0], [%1], 16;"
                             :: "r"(dst), "l"(src));
            }
        }
        asm volatile("cp.async.commit_group;" ::: "memory");
    };

    load_stage(0, 0);

    for (int it = 0; it < NIT; it++) {
        const int buf = it & 1;
        if (it + 1 < NIT) {
            load_stage(buf ^ 1, it + 1);
            asm volatile("cp.async.wait_group 1;" ::: "memory");
        } else {
            asm volatile("cp.async.wait_group 0;" ::: "memory");
        }
        __syncthreads();

        const char* A0 = sm + buf * GSTAGE_B;
        const char* A1 = A0 + GTILE_B;
        const char* B0 = A0 + 2 * GTILE_B;
        const char* B1 = A0 + 3 * GTILE_B;

#pragma unroll
        for (int ks = 0; ks < 2; ks++) {
            const int kb = ks * 32 + tig * 4;
            uint32_t bh[4][2], bl[4][2];
#pragma unroll
            for (int nt = 0; nt < 4; nt++) {
                int off = (warp_n * 32 + nt * 8 + g) * GP_B + kb;
                bh[nt][0] = *(const uint32_t*)(B0 + off);
                bh[nt][1] = *(const uint32_t*)(B0 + off + 16);
                bl[nt][0] = *(const uint32_t*)(B1 + off);
                bl[nt][1] = *(const uint32_t*)(B1 + off + 16);
            }
#pragma unroll
            for (int mt = 0; mt < 4; mt++) {
                uint32_t ah[4], al[4];
                int off = (warp_m * 64 + mt * 16 + g) * GP_B + kb;
                ah[0] = *(const uint32_t*)(A0 + off);
                ah[1] = *(const uint32_t*)(A0 + off + 8 * GP_B);
                ah[2] = *(const uint32_t*)(A0 + off + 16);
                ah[3] = *(const uint32_t*)(A0 + off + 8 * GP_B + 16);
                al[0] = *(const uint32_t*)(A1 + off);
                al[1] = *(const uint32_t*)(A1 + off + 8 * GP_B);
                al[2] = *(const uint32_t*)(A1 + off + 16);
                al[3] = *(const uint32_t*)(A1 + off + 8 * GP_B + 16);
#pragma unroll
                for (int nt = 0; nt < 4; nt++) {
                    mma16816(acc[mt][nt], ah, bh[nt]);
                    mma16816(acc[mt][nt], ah, bl[nt]);
                    mma16816(acc[mt][nt], al, bh[nt]);
                }
            }
        }
        __syncthreads();
    }

    // Epilogue
#pragma unroll
    for (int mt = 0; mt < 4; mt++) {
        int row0 = bm + warp_m * 64 + mt * 16 + g;
#pragma unroll
        for (int nt = 0; nt < 4; nt++) {
            int col = bn + warp_n * 32 + nt * 8 + 2 * tig;
            float bx = bias[col], by = bias[col + 1];
            float v00 = acc[mt][nt][0] + bx, v01 = acc[mt][nt][1] + by;
            float v10 = acc[mt][nt][2] + bx, v11 = acc[mt][nt][3] + by;
            if (relu) {
                v00 = fmaxf(v00, 0.f); v01 = fmaxf(v01, 0.f);
                v10 = fmaxf(v10, 0.f); v11 = fmaxf(v11, 0.f);
            }
            if (mode == 0) {
                *(float2*)&C[(size_t)row0 * N + col] = make_float2(v00, v01);
                *(float2*)&C[(size_t)(row0 + 8) * N + col] = make_float2(v10, v11);
            } else {
                float h00 = __bfloat162float(__float2bfloat16_rn(v00));
                float h01 = __bfloat162float(__float2bfloat16_rn(v01));
                float h10 = __bfloat162float(__float2bfloat16_rn(v10));
                float h11 = __bfloat162float(__float2bfloat16_rn(v11));
                *(uint32_t*)&Chi[(size_t)row0 * N + col] = pk2(h00, h01);
                *(uint32_t*)&Chi[(size_t)(row0 + 8) * N + col] = pk2(h10, h11);
                *(uint32_t*)&Clo[(size_t)row0 * N + col] = pk2(v00 - h00, v01 - h01);
                *(uint32_t*)&Clo[(size_t)(row0 + 8) * N + col] = pk2(v10 - h10, v11 - h11);
            }
        }
    }
}

// ---------------------------------------------------------------------------
// Tensor-core flash attention, causal, bf16x3 MMA, fp32 softmax.
// CTA: 128 q rows, 8 warps x 16 rows, KV tile 64. Writes split bf16 output.
// ---------------------------------------------------------------------------
#define AP 72   // smem pitch in bf16 elems (144B rows -> conflict-free frags)
#define ATT_SMEM ((2*128 + 4*64) * AP * 2)   // 73728 bytes

__global__ __launch_bounds__(256, 2) void attn_tc_kernel(
    const bf16* __restrict__ qhi, const bf16* __restrict__ qlo,
    const bf16* __restrict__ khi, const bf16* __restrict__ klo,
    const bf16* __restrict__ vhi, const bf16* __restrict__ vlo,
    bf16* __restrict__ thi, bf16* __restrict__ tlo) {
    extern __shared__ bf16 asmem[];
    bf16* Qh = asmem;
    bf16* Ql = Qh + 128 * AP;
    bf16* Kh = Ql + 128 * AP;
    bf16* Kl = Kh + 64 * AP;
    bf16* Vh = Kl + 64 * AP;   // transposed [d][kv^swz]
    bf16* Vl = Vh + 64 * AP;

    const int tid = threadIdx.x;
    const int lane = tid & 31;
    const int wid = tid >> 5;
    const int g = lane >> 2;
    const int tig = lane & 3;

    const int qb = blockIdx.x;
    const int bh = blockIdx.y;
    const int b = bh / HH;
    const int h = bh % HH;
    const int q0 = qb * 128;

    const size_t hoff = (size_t)h * DHH;

    // Load Q (128 x 64, hi+lo)
#pragma unroll
    for (int i = 0; i < 4; i++) {
        int idx = i * 256 + tid;
        int row = idx >> 3;
        int cb = (idx & 7) * 8;
        size_t go = (size_t)(b * SS + q0 + row) * DD + hoff + cb;
        *(uint4*)&Qh[row * AP + cb] = *(const uint4*)&qhi[go];
        *(uint4*)&Ql[row * AP + cb] = *(const uint4*)&qlo[go];
    }

    float oacc[8][4];
#pragma unroll
    for (int vn = 0; vn < 8; vn++)
#pragma unroll
        for (int e = 0; e < 4; e++) oacc[vn][e] = 0.f;
    float mrow[2] = {-1e30f, -1e30f};
    float lrow[2] = {0.f, 0.f};

    const int nkt = 2 * qb + 2;
    const int wr0 = q0 + wid * 16;          // warp's first q row
    const float scale = 0.125f;

    for (int kt = 0; kt < nkt; kt++) {
        const int k0 = kt * 64;
        __syncthreads();
        // load K (64x64) and V transposed
#pragma unroll
        for (int i = 0; i < 2; i++) {
            int idx = i * 256 + tid;
            int row = idx >> 3;
            int cb = (idx & 7) * 8;
            size_t go = (size_t)(b * SS + k0 + row) * DD + hoff + cb;
            *(uint4*)&Kh[row * AP + cb] = *(const uint4*)&khi[go];
            *(uint4*)&Kl[row * AP + cb] = *(const uint4*)&klo[go];
            // V: read 8 bf16 of row (kv=row, d=cb..cb+7), store transposed
            uint4 vh4 = *(const uint4*)&vhi[go];
            uint4 vl4 = *(const uint4*)&vlo[go];
            const bf16* ph = (const bf16*)&vh4;
            const bf16* pl = (const bf16*)&vl4;
#pragma unroll
            for (int e = 0; e < 8; e++) {
                int d = cb + e;
                int kvs = row ^ (((d >> 3) & 7) << 1);
                Vh[d * AP + kvs] = ph[e];
                Vl[d * AP + kvs] = pl[e];
            }
        }
        __syncthreads();

        if (k0 <= wr0 + 15) {   // warp has at least one unmasked row
            // ---- S = Q K^T ----
            float sacc[8][4];
#pragma unroll
            for (int nt = 0; nt < 8; nt++)
#pragma unroll
                for (int e = 0; e < 4; e++) sacc[nt][e] = 0.f;

#pragma unroll
            for (int kc = 0; kc < 4; kc++) {
                uint32_t ah[4], al[4];
                int aoff = (wid * 16 + g) * AP + kc * 16 + 2 * tig;
                ah[0] = *(const uint32_t*)&Qh[aoff];
                ah[1] = *(const uint32_t*)&Qh[aoff + 8 * AP];
                ah[2] = *(const uint32_t*)&Qh[aoff + 8];
                ah[3] = *(const uint32_t*)&Qh[aoff + 8 * AP + 8];
                al[0] = *(const uint32_t*)&Ql[aoff];
                al[1] = *(const uint32_t*)&Ql[aoff + 8 * AP];
                al[2] = *(const uint32_t*)&Ql[aoff + 8];
                al[3] = *(const uint32_t*)&Ql[aoff + 8 * AP + 8];
#pragma unroll
                for (int nt = 0; nt < 8; nt++) {
                    int boff = (nt * 8 + g) * AP + kc * 16 + 2 * tig;
                    uint32_t bh2[2], bl2[2];
                    bh2[0] = *(const uint32_t*)&Kh[boff];
                    bh2[1] = *(const uint32_t*)&Kh[boff + 8];
                    bl2[0] = *(const uint32_t*)&Kl[boff];
                    bl2[1] = *(const uint32_t*)&Kl[boff + 8];
                    mma16816(sacc[nt], ah, bh2);
                    mma16816(sacc[nt], ah, bl2);
                    mma16816(sacc[nt], al, bh2);
                }
            }

            // scale + causal mask
            const bool needmask = (k0 + 63) > wr0;
#pragma unroll
            for (int nt = 0; nt < 8; nt++)
#pragma unroll
                for (int e = 0; e < 4; e++) {
                    float sv = sacc[nt][e] * scale;
                    if (needmask) {
                        int row = wr0 + g + ((e >> 1) << 3);
                        int col = k0 + nt * 8 + 2 * tig + (e & 1);
                        if (col > row) sv = -1e30f;
                    }
                    sacc[nt][e] = sv;
                }

            // online softmax (rows g, g+8; quad reduce over tig lanes)
#pragma unroll
            for (int rr = 0; rr < 2; rr++) {
                float mx = -1e30f;
#pragma unroll
                for (int nt = 0; nt < 8; nt++)
                    mx = fmaxf(mx, fmaxf(sacc[nt][2 * rr], sacc[nt][2 * rr + 1]));
                mx = fmaxf(mx, __shfl_xor_sync(0xffffffffu, mx, 1));
                mx = fmaxf(mx, __shfl_xor_sync(0xffffffffu, mx, 2));
                float mnew = fmaxf(mrow[rr], mx);
                float alpha = __expf(mrow[rr] - mnew);
                float rs = 0.f;
#pragma unroll
                for (int nt = 0; nt < 8; nt++) {
                    float p0 = __expf(sacc[nt][2 * rr] - mnew);
                    float p1 = __expf(sacc[nt][2 * rr + 1] - mnew);
                    sacc[nt][2 * rr] = p0;
                    sacc[nt][2 * rr + 1] = p1;
                    rs += p0 + p1;
                }
                rs += __shfl_xor_sync(0xffffffffu, rs, 1);
                rs += __shfl_xor_sync(0xffffffffu, rs, 2);
                lrow[rr] = lrow[rr] * alpha + rs;
                mrow[rr] = mnew;
#pragma unroll
                for (int vn = 0; vn < 8; vn++) {
                    oacc[vn][2 * rr] *= alpha;
                    oacc[vn][2 * rr + 1] *= alpha;
                }
            }

            // ---- O += P V ----
#pragma unroll
            for (int kc2 = 0; kc2 < 4; kc2++) {
                float* t0 = sacc[2 * kc2];
                float* t1 = sacc[2 * kc2 + 1];
                float h00 = __bfloat162float(__float2bfloat16_rn(t0[0]));
                float h01 = __bfloat162float(__float2bfloat16_rn(t0[1]));
                float h02 = __bfloat162float(__float2bfloat16_rn(t0[2]));
                float h03 = __bfloat162float(__float2bfloat16_rn(t0[3]));
                float h10 = __bfloat162float(__float2bfloat16_rn(t1[0]));
                float h11 = __bfloat162float(__float2bfloat16_rn(t1[1]));
                float h12 = __bfloat162float(__float2bfloat16_rn(t1[2]));
                float h13 = __bfloat162float(__float2bfloat16_rn(t1[3]));
                uint32_t ph[4], pl[4];
                ph[0] = pk2(h00, h01); ph[1] = pk2(h02, h03);
                ph[2] = pk2(h10, h11); ph[3] = pk2(h12, h13);
                pl[0] = pk2(t0[0] - h00, t0[1] - h01);
                pl[1] = pk2(t0[2] - h02, t0[3] - h03);
                pl[2] = pk2(t1[0] - h10, t1[1] - h11);
                pl[3] = pk2(t1[2] - h12, t1[3] - h13);
                int kvc = kc2 * 16 + 2 * tig;
#pragma unroll
                for (int vn = 0; vn < 8; vn++) {
                    int swz = (vn << 1);
                    int boff = (vn * 8 + g) * AP;
                    uint32_t bh2[2], bl2[2];
                    bh2[0] = *(const uint32_t*)&Vh[boff + (kvc ^ swz)];
                    bh2[1] = *(const uint32_t*)&Vh[boff + ((kvc + 8) ^ swz)];
                    bl2[0] = *(const uint32_t*)&Vl[boff + (kvc ^ swz)];
                    bl2[1] = *(const uint32_t*)&Vl[boff + ((kvc + 8) ^ swz)];
                    mma16816(oacc[vn], ph, bh2);
                    mma16816(oacc[vn], pl, bh2);
                    mma16816(oacc[vn], ph, bl2);
                }
            }
        }
    }

    // epilogue: normalize + split-store
#pragma unroll
    for (int rr = 0; rr < 2; rr++) {
        float inv = 1.f / lrow[rr];
        int r = wr0 + g + rr * 8;
        size_t rb = (size_t)(b * SS + r) * DD + hoff;
#pragma unroll
        for (int vn = 0; vn < 8; vn++) {
            float o0 = oacc[vn][2 * rr] * inv;
            float o1 = oacc[vn][2 * rr + 1] * inv;
            float h0 = __bfloat162float(__float2bfloat16_rn(o0));
            float h1 = __bfloat162float(__float2bfloat16_rn(o1));
            int col = vn * 8 + 2 * tig;
            *(uint32_t*)&thi[rb + col] = pk2(h0, h1);
            *(uint32_t*)&tlo[rb + col] = pk2(o0 - h0, o1 - h1);
        }
    }
}

// ---------------------------------------------------------------------------
// Residual add + LayerNorm: x = LN(x+y)*g+b (in-place) + split bf16 out
// ---------------------------------------------------------------------------
__global__ __launch_bounds__(256) void add_ln_kernel(float* __restrict__ x,
                                                     const float* __restrict__ y,
                                                     const float* __restrict__ g,
                                                     const float* __restrict__ bb,
                                                     bf16* __restrict__ xhi,
                                                     bf16* __restrict__ xlo) {
    const int row = blockIdx.x;
    const int tid = threadIdx.x;
    float2 xv = *(const float2*)&x[(size_t)row * DD + tid * 2];
    float2 yv = *(const float2*)&y[(size_t)row * DD + tid * 2];
    float a0 = xv.x + yv.x;
    float a1 = xv.y + yv.y;

    float s = a0 + a1;
    float ss = a0 * a0 + a1 * a1;
#pragma unroll
    for (int off = 16; off >= 1; off >>= 1) {
        s += __shfl_xor_sync(0xffffffffu, s, off);
        ss += __shfl_xor_sync(0xffffffffu, ss, off);
    }
    __shared__ float sbuf[8], ssbuf[8];
    if ((tid & 31) == 0) { sbuf[tid >> 5] = s; ssbuf[tid >> 5] = ss; }
    __syncthreads();
    float ts = 0.f, tss = 0.f;
#pragma unroll
    for (int i = 0; i < 8; i++) { ts += sbuf[i]; tss += ssbuf[i]; }
    float mean = ts * (1.f / DD);
    float var = tss * (1.f / DD) - mean * mean;
    float rstd = rsqrtf(var + 1e-5f);

    int col = tid * 2;
    float2 go = *(const float2*)&g[col];
    float2 bo = *(const float2*)&bb[col];
    float o0 = (a0 - mean) * rstd * go.x + bo.x;
    float o1 = (a1 - mean) * rstd * go.y + bo.y;
    *(float2*)&x[(size_t)row * DD + col] = make_float2(o0, o1);
    float h0 = __bfloat162float(__float2bfloat16_rn(o0));
    float h1 = __bfloat162float(__float2bfloat16_rn(o1));
    *(uint32_t*)&xhi[(size_t)row * DD + col] = pk2(h0, h1);
    *(uint32_t*)&xlo[(size_t)row * DD + col] = pk2(o0 - h0, o1 - h1);
}

// ---------------------------------------------------------------------------
// Host driver
// ---------------------------------------------------------------------------
extern "C" void kernel_launch(void* const* d_in, const int* in_sizes, int n_in,
                              void* d_out, int out_size) {
    const int* source = (const int*)d_in[0];
    const float* emb = (const float*)d_in[1];
    const float* ln_g = (const float*)d_in[2];
    const float* ln_b = (const float*)d_in[3];
    const float* wq = (const float*)d_in[4];
    const float* bq = (const float*)d_in[5];
    const float* wk = (const float*)d_in[6];
    const float* bk = (const float*)d_in[7];
    const float* wv = (const float*)d_in[8];
    const float* bv = (const float*)d_in[9];
    const float* wo = (const float*)d_in[10];
    const float* bo = (const float*)d_in[11];
    const float* w1 = (const float*)d_in[12];
    const float* b1 = (const float*)d_in[13];
    const float* w2 = (const float*)d_in[14];
    const float* b2 = (const float*)d_in[15];

    float* x = (float*)d_out;

    float* tmp;
    bf16 *xhi, *xlo, *qhi, *qlo, *khi, *klo, *vhi, *vlo, *thi, *tlo, *hhi, *hlo, *wthi, *wtlo;
    cudaGetSymbolAddress((void**)&tmp, g_tmp);
    cudaGetSymbolAddress((void**)&xhi, g_xhi);
    cudaGetSymbolAddress((void**)&xlo, g_xlo);
    cudaGetSymbolAddress((void**)&qhi, g_qhi);
    cudaGetSymbolAddress((void**)&qlo, g_qlo);
    cudaGetSymbolAddress((void**)&khi, g_khi);
    cudaGetSymbolAddress((void**)&klo, g_klo);
    cudaGetSymbolAddress((void**)&vhi, g_vhi);
    cudaGetSymbolAddress((void**)&vlo, g_vlo);
    cudaGetSymbolAddress((void**)&thi, g_thi);
    cudaGetSymbolAddress((void**)&tlo, g_tlo);
    cudaGetSymbolAddress((void**)&hhi, g_hhi);
    cudaGetSymbolAddress((void**)&hlo, g_hlo);
    cudaGetSymbolAddress((void**)&wthi, g_wthi);
    cudaGetSymbolAddress((void**)&wtlo, g_wtlo);

    cudaFuncSetAttribute(attn_tc_kernel, cudaFuncAttributeMaxDynamicSharedMemorySize,
                         ATT_SMEM);
    cudaFuncSetAttribute(gemm_wm_kernel, cudaFuncAttributeMaxDynamicSharedMemorySize,
                         GSMEM);

    embed_kernel<<<NROWS, 128>>>(source, emb, x, xhi, xlo);

    dim3 gA(SS / 128, BB * HH);

    auto gemm = [&](const bf16* ah, const bf16* al, const bf16* bh, const bf16* bl,
                    const float* bias, float* C, bf16* Ch, bf16* Cl,
                    int M, int N, int K, int relu, int mode) {
        dim3 g(N / 128, M / 128);
        gemm_wm_kernel<<<g, 256, GSMEM>>>(ah, al, bh, bl, bias, C, Ch, Cl,
                                          M, N, K, relu, mode);
    };

    for (int l = 0; l < LL; l++) {
        const float* Wq = wq + (size_t)l * DD * DD;
        const float* Bq = bq + (size_t)l * DD;
        const float* Wk = wk + (size_t)l * DD * DD;
        const float* Bk = bk + (size_t)l * DD;
        const float* Wv = wv + (size_t)l * DD * DD;
        const float* Bv = bv + (size_t)l * DD;
        const float* Wo = wo + (size_t)l * DD * DD;
        const float* Bo = bo + (size_t)l * DD;
        const float* W1 = w1 + (size_t)l * DD * FF;
        const float* B1 = b1 + (size_t)l * FF;
        const float* W2 = w2 + (size_t)l * FF * DD;
        const float* B2 = b2 + (size_t)l * DD;

        // QKV projections -> split bf16 outputs
        transpose_cvt_kernel<<<dim3(DD / 32, DD / 32), 256>>>(Wq, wthi, wtlo, DD, DD);
        gemm(xhi, xlo, wthi, wtlo, Bq, nullptr, qhi, qlo, NROWS, DD, DD, 0, 1);
        transpose_cvt_kernel<<<dim3(DD / 32, DD / 32), 256>>>(Wk, wthi, wtlo, DD, DD);
        gemm(xhi, xlo, wthi, wtlo, Bk, nullptr, khi, klo, NROWS, DD, DD, 0, 1);
        transpose_cvt_kernel<<<dim3(DD / 32, DD / 32), 256>>>(Wv, wthi, wtlo, DD, DD);
        gemm(xhi, xlo, wthi, wtlo, Bv, nullptr, vhi, vlo, NROWS, DD, DD, 0, 1);

        attn_tc_kernel<<<gA, 256, ATT_SMEM>>>(qhi, qlo, khi, klo, vhi, vlo, thi, tlo);

        // output projection -> fp32, then add+LN -> x + split
        transpose_cvt_kernel<<<dim3(DD / 32, DD / 32), 256>>>(Wo, wthi, wtlo, DD, DD);
        gemm(thi, tlo, wthi, wtlo, Bo, tmp, nullptr, nullptr, NROWS, DD, DD, 0, 0);
        add_ln_kernel<<<NROWS, 256>>>(x, tmp, ln_g, ln_b, xhi, xlo);

        // FFN
        transpose_cvt_kernel<<<dim3(FF / 32, DD / 32), 256>>>(W1, wthi, wtlo, DD, FF);
        gemm(xhi, xlo, wthi, wtlo, B1, nullptr, hhi, hlo, NROWS, FF, DD, 1, 1);
        transpose_cvt_kernel<<<dim3(DD / 32, FF / 32), 256>>>(W2, wthi, wtlo, FF, DD);
        gemm(hhi, hlo, wthi, wtlo, B2, tmp, nullptr, nullptr, NROWS, DD, FF, 1, 0);
        add_ln_kernel<<<NROWS, 256>>>(x, tmp, ln_g, ln_b, xhi, xlo);
    }
}